// round 1
// baseline (speedup 1.0000x reference)
#include <cuda_runtime.h>
#include <math.h>

// Partial results per (b,t) tile. 112 tiles for B=4,T=28; pad generously.
#define MAXBT 1024
__device__ float g_loss_part[MAXBT];
__device__ float g_lossc_part[MAXBT];

__device__ __forceinline__ float sl1(float a, float b) {
    float d = fabsf(a - b);
    return d < 1.0f ? 0.5f * d * d : d - 0.5f;
}

// Block reduce (sum). Result valid in thread 0. red must hold >= 32 floats.
__device__ __forceinline__ float blockReduceSum(float v, float* red) {
    #pragma unroll
    for (int o = 16; o > 0; o >>= 1)
        v += __shfl_down_sync(0xffffffffu, v, o);
    int lane = threadIdx.x & 31;
    int wid  = threadIdx.x >> 5;
    __syncthreads();                 // protect red across repeated calls
    if (lane == 0) red[wid] = v;
    __syncthreads();
    if (wid == 0) {
        int nw = blockDim.x >> 5;
        v = (lane < nw) ? red[lane] : 0.0f;
        #pragma unroll
        for (int o = 16; o > 0; o >>= 1)
            v += __shfl_down_sync(0xffffffffu, v, o);
    }
    return v;
}

// One CTA per (b,t). blockDim.x == N (1024). Each thread owns one pred point,
// scans all N targets staged in smem as float4(-2tx,-2ty,-2tz, |t|^2).
__global__ __launch_bounds__(1024, 1)
void nn_loss_kernel(const float* __restrict__ X,
                    const float* __restrict__ T,
                    const float* __restrict__ W,
                    int N)
{
    extern __shared__ float4 tgt[];      // N float4 = 16KB for N=1024
    __shared__ float red[32];

    const int bt  = blockIdx.x;
    const int tid = threadIdx.x;
    const float* Xb = X + (size_t)bt * N * 3;
    const float* Tb = T + (size_t)bt * N * 3;

    // Stage target point tid: pre-scale by -2 and append squared norm.
    float t0 = Tb[tid * 3 + 0];
    float t1 = Tb[tid * 3 + 1];
    float t2 = Tb[tid * 3 + 2];
    float tn = fmaf(t0, t0, fmaf(t1, t1, t2 * t2));
    tgt[tid] = make_float4(-2.0f * t0, -2.0f * t1, -2.0f * t2, tn);

    // This thread's pred point.
    float x0 = Xb[tid * 3 + 0];
    float x1 = Xb[tid * 3 + 1];
    float x2 = Xb[tid * 3 + 2];

    __syncthreads();

    // Brute-force argmin over targets. Key = |t|^2 - 2*x.t  (monotone in
    // true squared distance since |x|^2 is constant per thread).
    // Strict '<' with ascending m reproduces jnp.argmin first-min tie-break.
    float best = 3.402823466e+38f;
    int   bidx = 0;
    #pragma unroll 8
    for (int m = 0; m < N; ++m) {
        float4 t = tgt[m];          // broadcast LDS.128 (all lanes same m)
        float d = fmaf(x0, t.x, fmaf(x1, t.y, fmaf(x2, t.z, t.w)));
        if (d < best) { best = d; bidx = m; }
    }

    // Gather the winning target (undo the -2 prescale) and smooth-L1.
    float4 tb = tgt[bidx];
    float s = sl1(x0, -0.5f * tb.x)
            + sl1(x1, -0.5f * tb.y)
            + sl1(x2, -0.5f * tb.z);

    // Block reductions: smooth-L1 sum, pred coord sums, target coord sums.
    float S   = blockReduceSum(s,  red);
    float sx0 = blockReduceSum(x0, red);
    float sx1 = blockReduceSum(x1, red);
    float sx2 = blockReduceSum(x2, red);
    float st0 = blockReduceSum(t0, red);
    float st1 = blockReduceSum(t1, red);
    float st2 = blockReduceSum(t2, red);

    if (tid == 0) {
        g_loss_part[bt] = W[bt] * S;   // weighted sum of per-point sl1; scaled later
        float inv = 1.0f / (float)N;
        g_lossc_part[bt] = sl1(sx0 * inv, st0 * inv)
                         + sl1(sx1 * inv, st1 * inv)
                         + sl1(sx2 * inv, st2 * inv);
    }
}

// Deterministic single-warp finalize: out[0] = loss, out[1] = lossc.
__global__ void finalize_kernel(float* __restrict__ out, int BT, int N, int B)
{
    float s1 = 0.0f, s2 = 0.0f;
    for (int i = threadIdx.x; i < BT; i += 32) {
        s1 += g_loss_part[i];
        s2 += g_lossc_part[i];
    }
    #pragma unroll
    for (int o = 16; o > 0; o >>= 1) {
        s1 += __shfl_down_sync(0xffffffffu, s1, o);
        s2 += __shfl_down_sync(0xffffffffu, s2, o);
    }
    if (threadIdx.x == 0) {
        out[0] = s1 / (3.0f * (float)N * (float)B);   // mean over (N,3), weighted sum, /B
        out[1] = s2 / ((float)B * 3.0f);
    }
}

extern "C" void kernel_launch(void* const* d_in, const int* in_sizes, int n_in,
                              void* d_out, int out_size)
{
    const float* X = (const float*)d_in[0];   // [B,T,N,3]
    const float* T = (const float*)d_in[1];   // [B,T,N,3]
    const float* W = (const float*)d_in[2];   // [B,T]
    float* out = (float*)d_out;

    const int BT = in_sizes[2];               // B*T = 112
    const int N  = in_sizes[0] / (BT * 3);    // 1024
    const int B  = 4;                         // fixed by problem setup

    size_t smem = (size_t)N * sizeof(float4);
    nn_loss_kernel<<<BT, N, smem>>>(X, T, W, N);
    finalize_kernel<<<1, 32>>>(out, BT, N, B);
}

// round 2
// speedup vs baseline: 1.0106x; 1.0106x over previous
#include <cuda_runtime.h>
#include <math.h>
#include <float.h>

#define MAXBT 1024
__device__ float g_loss_part[MAXBT];
__device__ float g_lossc_part[MAXBT];
__device__ unsigned int g_count;

typedef unsigned long long u64;

__device__ __forceinline__ u64 pk2(float lo, float hi) {
    u64 r; asm("mov.b64 %0, {%1,%2};" : "=l"(r) : "f"(lo), "f"(hi)); return r;
}
__device__ __forceinline__ void upk2(float& lo, float& hi, u64 v) {
    asm("mov.b64 {%0,%1}, %2;" : "=f"(lo), "=f"(hi) : "l"(v));
}
__device__ __forceinline__ u64 ffma2(u64 a, u64 b, u64 c) {
    u64 d; asm("fma.rn.f32x2 %0, %1, %2, %3;" : "=l"(d) : "l"(a), "l"(b), "l"(c)); return d;
}

__device__ __forceinline__ float sl1(float a, float b) {
    float d = fabsf(a - b);
    return d < 1.0f ? 0.5f * d * d : d - 0.5f;
}

__device__ __forceinline__ float blockReduceSum(float v, float* red) {
    #pragma unroll
    for (int o = 16; o > 0; o >>= 1)
        v += __shfl_down_sync(0xffffffffu, v, o);
    int lane = threadIdx.x & 31;
    int wid  = threadIdx.x >> 5;
    __syncthreads();
    if (lane == 0) red[wid] = v;
    __syncthreads();
    if (wid == 0) {
        v = (lane < (int)(blockDim.x >> 5)) ? red[lane] : 0.0f;
        #pragma unroll
        for (int o = 16; o > 0; o >>= 1)
            v += __shfl_down_sync(0xffffffffu, v, o);
    }
    return v;
}

// One CTA per (b,t). 1024 threads, one pred point each. Targets staged in smem
// as paired layout for f32x2 math:
//   sA[m2] = (-2tx[2m2], -2tx[2m2+1], -2ty[2m2], -2ty[2m2+1])
//   sB[m2] = (-2tz[2m2], -2tz[2m2+1],  tn[2m2],  tn[2m2+1])
__global__ __launch_bounds__(1024, 1)
void nn_loss_kernel(const float* __restrict__ X,
                    const float* __restrict__ T,
                    const float* __restrict__ W,
                    float* __restrict__ out,
                    int N, int BT, int B)
{
    extern __shared__ float4 smem4[];
    float4* sA = smem4;            // N/2 float4
    float4* sB = smem4 + (N >> 1); // N/2 float4
    __shared__ float red[32];
    __shared__ int isLast;

    const int bt  = blockIdx.x;
    const int tid = threadIdx.x;
    const float* Xb = X + (size_t)bt * N * 3;
    const float* Tb = T + (size_t)bt * N * 3;

    // Stage target tid.
    float t0 = Tb[tid * 3 + 0];
    float t1 = Tb[tid * 3 + 1];
    float t2 = Tb[tid * 3 + 2];
    float tn = fmaf(t0, t0, fmaf(t1, t1, t2 * t2));
    {
        int m2 = tid >> 1, par = tid & 1;
        float* A = (float*)&sA[m2];
        float* Bp = (float*)&sB[m2];
        A[par]      = -2.0f * t0;
        A[2 + par]  = -2.0f * t1;
        Bp[par]     = -2.0f * t2;
        Bp[2 + par] = tn;
    }

    float x0 = Xb[tid * 3 + 0];
    float x1 = Xb[tid * 3 + 1];
    float x2 = Xb[tid * 3 + 2];

    __syncthreads();

    // Argmin scan, 2 targets per step via packed f32x2 FMA.
    // key = tn - 2*x.t  (monotone in true sq-dist; |x|^2 per-thread const).
    u64 xx0 = pk2(x0, x0), xx1 = pk2(x1, x1), xx2 = pk2(x2, x2);
    const ulonglong2* pA = (const ulonglong2*)sA;
    const ulonglong2* pB = (const ulonglong2*)sB;

    float best = FLT_MAX;
    int bidx = 0;
    const int half = N >> 1;
    #pragma unroll 8
    for (int m2 = 0; m2 < half; ++m2) {
        ulonglong2 a = pA[m2];   // (tx0,tx1), (ty0,ty1)  [prescaled by -2]
        ulonglong2 b = pB[m2];   // (tz0,tz1), (tn0,tn1)
        u64 dp = ffma2(xx0, a.x, ffma2(xx1, a.y, ffma2(xx2, b.x, b.y)));
        float d0, d1;
        upk2(d0, d1, dp);
        int m = m2 << 1;
        if (d0 < best) { best = d0; bidx = m; }
        if (d1 < best) { best = d1; bidx = m + 1; }
    }

    // Recover winning target coords (undo -2 prescale).
    int bm2 = bidx >> 1, bp = bidx & 1;
    const float* Af = (const float*)&sA[bm2];
    const float* Bf = (const float*)&sB[bm2];
    float bt0 = -0.5f * Af[bp];
    float bt1 = -0.5f * Af[2 + bp];
    float bt2 = -0.5f * Bf[bp];

    float s = sl1(x0, bt0) + sl1(x1, bt1) + sl1(x2, bt2);

    float S   = blockReduceSum(s,  red);
    float sx0 = blockReduceSum(x0, red);
    float sx1 = blockReduceSum(x1, red);
    float sx2 = blockReduceSum(x2, red);
    float st0 = blockReduceSum(t0, red);
    float st1 = blockReduceSum(t1, red);
    float st2 = blockReduceSum(t2, red);

    if (tid == 0) {
        g_loss_part[bt] = W[bt] * S;
        float inv = 1.0f / (float)N;
        g_lossc_part[bt] = sl1(sx0 * inv, st0 * inv)
                         + sl1(sx1 * inv, st1 * inv)
                         + sl1(sx2 * inv, st2 * inv);
        __threadfence();
        unsigned int prev = atomicAdd(&g_count, 1u);
        isLast = (prev == (unsigned int)(gridDim.x - 1)) ? 1 : 0;
    }
    __syncthreads();

    // Last CTA finalizes with warp 0 (deterministic order).
    if (isLast && tid < 32) {
        __threadfence();
        float s1 = 0.0f, s2 = 0.0f;
        for (int i = tid; i < BT; i += 32) {
            s1 += g_loss_part[i];
            s2 += g_lossc_part[i];
        }
        #pragma unroll
        for (int o = 16; o > 0; o >>= 1) {
            s1 += __shfl_down_sync(0xffffffffu, s1, o);
            s2 += __shfl_down_sync(0xffffffffu, s2, o);
        }
        if (tid == 0) {
            out[0] = s1 / (3.0f * (float)N * (float)B);
            out[1] = s2 / ((float)B * 3.0f);
            g_count = 0;   // reset for next graph replay
        }
    }
}

extern "C" void kernel_launch(void* const* d_in, const int* in_sizes, int n_in,
                              void* d_out, int out_size)
{
    const float* X = (const float*)d_in[0];   // [B,T,N,3]
    const float* T = (const float*)d_in[1];   // [B,T,N,3]
    const float* W = (const float*)d_in[2];   // [B,T]
    float* out = (float*)d_out;

    const int BT = in_sizes[2];               // 112
    const int N  = in_sizes[0] / (BT * 3);    // 1024
    const int B  = 4;

    size_t smem = (size_t)N * sizeof(float4); // 16 KB
    nn_loss_kernel<<<BT, N, smem>>>(X, T, W, out, N, BT, B);
}